// round 1
// baseline (speedup 1.0000x reference)
#include <cuda_runtime.h>
#include <cuda_bf16.h>

// PitchLoss: the reference's (N,B,L) broadcast collapses analytically because
// mask[n,b,l] = c[b,n] is constant over l:
//   diff[b,n] = | c[b,n] * (mean_g[b] - mean_t[b]) / (c[b,n] + 1e-6) |
//   loss      = mean_{b,n} relu(diff - 0.5)
// where c[b,n] = -(# onsets with idx>=1 in segment n) - (n==0 ? offsets[b,0] : 0),
// zeroed where n >= n_notes[b] = sum_l offsets[b,l], segment index = inclusive
// cumsum of offsets.

#define BATCH 64
#define LEN   4096
#define NMAX  128
#define T1    512
#define CHUNK (LEN / T1)   // 8 elements per thread

__device__ float g_partial[BATCH];

__global__ __launch_bounds__(T1)
void pitch_row_kernel(const float* __restrict__ gen_f0,
                      const float* __restrict__ contours,
                      const int*   __restrict__ onsets,
                      const int*   __restrict__ offsets)
{
    const int b   = blockIdx.x;
    const int tid = threadIdx.x;

    const float* gr  = gen_f0   + (size_t)b * LEN;       // gen_f0[b,0,:]
    const float* tr  = contours + (size_t)b * 2 * LEN;   // contours[b,0,:]
    const int*   on  = onsets   + (size_t)b * LEN;
    const int*   off = offsets  + (size_t)b * LEN;

    __shared__ int   s_counts[NMAX];
    __shared__ int   s_scan[T1];
    __shared__ float s_redg[T1];
    __shared__ float s_redt[T1];
    __shared__ float s_dd;
    __shared__ int   s_nnotes;
    __shared__ int   s_off0;

    for (int i = tid; i < NMAX; i += T1) s_counts[i] = 0;

    // ---- pass 1: per-thread partial sums + local offset count ----
    const int base = tid * CHUNK;
    float sg = 0.f, st = 0.f;
    int   osum = 0;
    int   loc_off[CHUNK];
    int   loc_on[CHUNK];
#pragma unroll
    for (int j = 0; j < CHUNK; j++) {
        const int l = base + j;
        sg += gr[l];
        st += tr[l];
        loc_off[j] = off[l];
        loc_on[j]  = on[l];
        osum += loc_off[j];
    }
    s_redg[tid] = sg;
    s_redt[tid] = st;
    s_scan[tid] = osum;
    __syncthreads();

    // ---- tree-reduce the two float sums ----
    for (int s = T1 / 2; s > 0; s >>= 1) {
        if (tid < s) {
            s_redg[tid] += s_redg[tid + s];
            s_redt[tid] += s_redt[tid + s];
        }
        __syncthreads();
    }

    // ---- inclusive block scan of per-thread offset counts (Hillis-Steele) ----
    for (int d = 1; d < T1; d <<= 1) {
        const int add = (tid >= d) ? s_scan[tid - d] : 0;
        __syncthreads();
        s_scan[tid] += add;
        __syncthreads();
    }

    // ---- pass 2: scatter onset counts into segment histogram ----
    // segment index at position l is the INCLUSIVE cumsum of offsets up to l.
    int run = (tid == 0) ? 0 : s_scan[tid - 1];
#pragma unroll
    for (int j = 0; j < CHUNK; j++) {
        const int l = base + j;
        run += loc_off[j];
        if (l >= 1 && loc_on[j] && run < NMAX)
            atomicAdd(&s_counts[run], 1);
    }

    if (tid == 0) {
        s_dd     = (s_redg[0] - s_redt[0]) * (1.0f / LEN);  // mean_g - mean_t
        s_nnotes = s_scan[T1 - 1];                           // total offsets
        s_off0   = off[0];
    }
    __syncthreads();

    // ---- per-note loss contribution ----
    float val = 0.f;
    if (tid < NMAX) {
        float c = -(float)s_counts[tid];
        if (tid == 0) c -= (float)s_off0;
        if (tid >= s_nnotes) c = 0.f;
        const float diff = fabsf(c * s_dd / (c + 1e-6f));
        val = fmaxf(diff - 0.5f, 0.f);
    }
    s_redg[tid] = val;   // threads >= NMAX contribute 0
    __syncthreads();
    for (int s = T1 / 2; s > 0; s >>= 1) {
        if (tid < s) s_redg[tid] += s_redg[tid + s];
        __syncthreads();
    }
    if (tid == 0) g_partial[b] = s_redg[0];
}

__global__ void pitch_final_kernel(float* __restrict__ out)
{
    __shared__ float s[BATCH];
    const int tid = threadIdx.x;
    s[tid] = g_partial[tid];
    __syncthreads();
    for (int k = BATCH / 2; k > 0; k >>= 1) {
        if (tid < k) s[tid] += s[tid + k];
        __syncthreads();
    }
    if (tid == 0) out[0] = s[0] * (1.0f / (NMAX * BATCH));
}

extern "C" void kernel_launch(void* const* d_in, const int* in_sizes, int n_in,
                              void* d_out, int out_size)
{
    const float* gen_f0   = (const float*)d_in[0];
    const float* contours = (const float*)d_in[1];
    const int*   onsets   = (const int*)d_in[2];
    const int*   offsets  = (const int*)d_in[3];
    // d_in[4] = n_notes_max (compile-time constant NMAX=128 for this shape)

    pitch_row_kernel<<<BATCH, T1>>>(gen_f0, contours, onsets, offsets);
    pitch_final_kernel<<<1, BATCH>>>((float*)d_out);
}

// round 3
// speedup vs baseline: 1.1500x; 1.1500x over previous
#include <cuda_runtime.h>
#include <cuda_bf16.h>

// PitchLoss: the reference's (N,B,L) broadcast collapses analytically because
// mask[n,b,l] = c[b,n] is constant over l:
//   diff[b,n] = | c[b,n] * (mean_g[b] - mean_t[b]) / (c[b,n] + 1e-6) |
//   loss      = mean_{b,n} relu(diff - 0.5)
// with c[b,n] = -(# onsets at idx>=1 in segment n) - (n==0 ? offsets[b,0] : 0),
// zeroed for n >= n_notes[b] = sum_l offsets[b,l]; segment index = inclusive
// cumsum of offsets. Single fused kernel: 64 blocks (one per batch row),
// last block to finish reduces the 64 partials (threadfence + atomic ticket,
// no spin -> no deadlock, ticket self-resets for graph replay).

#define BATCH 64
#define LEN   4096
#define NMAX  128
#define T1    256
#define CHUNK (LEN / T1)   // 16 elements / thread, one 16-bit mask each
#define FULLM 0xffffffffu

__device__ float g_partial[BATCH];
__device__ int   g_ticket = 0;

__global__ __launch_bounds__(T1)
void pitch_fused_kernel(const float* __restrict__ gen_f0,
                        const float* __restrict__ contours,
                        const int*   __restrict__ onsets,
                        const int*   __restrict__ offsets,
                        float*       __restrict__ out)
{
    const int b    = blockIdx.x;
    const int tid  = threadIdx.x;
    const int lane = tid & 31;
    const int wid  = tid >> 5;           // 8 warps

    const float4* gr  = (const float4*)(gen_f0   + (size_t)b * LEN)     + tid * (CHUNK / 4);
    const float4* tr  = (const float4*)(contours + (size_t)b * 2 * LEN) + tid * (CHUNK / 4);
    const int4*   on  = (const int4*)(onsets  + (size_t)b * LEN) + tid * (CHUNK / 4);
    const int4*   off = (const int4*)(offsets + (size_t)b * LEN) + tid * (CHUNK / 4);

    __shared__ int   s_counts[NMAX];
    __shared__ int   s_wosum[8];
    __shared__ float s_wg[8], s_wt[8];
    __shared__ float s_red[4];
    __shared__ int   s_off0;
    __shared__ int   s_islast;

    if (tid < NMAX) s_counts[tid] = 0;

    // ---- vectorized loads: sums + 16-bit on/off masks ----
    float sg = 0.f, st = 0.f;
    unsigned offm = 0, onm = 0;
#pragma unroll
    for (int j = 0; j < CHUNK / 4; j++) {
        float4 g4 = gr[j];
        float4 t4 = tr[j];
        int4   o4 = off[j];
        int4   n4 = on[j];
        sg += (g4.x + g4.y) + (g4.z + g4.w);
        st += (t4.x + t4.y) + (t4.z + t4.w);
        const int s = 4 * j;
        offm |= ((unsigned)o4.x << s) | ((unsigned)o4.y << (s + 1))
              | ((unsigned)o4.z << (s + 2)) | ((unsigned)o4.w << (s + 3));
        onm  |= ((unsigned)n4.x << s) | ((unsigned)n4.y << (s + 1))
              | ((unsigned)n4.z << (s + 2)) | ((unsigned)n4.w << (s + 3));
    }
    const int osum = __popc(offm);

    // ---- warp-level: inclusive scan of osum, reduce sg/st ----
    int incl = osum;
#pragma unroll
    for (int d = 1; d < 32; d <<= 1) {
        int v = __shfl_up_sync(FULLM, incl, d);
        if (lane >= d) incl += v;
    }
#pragma unroll
    for (int d = 16; d > 0; d >>= 1) {
        sg += __shfl_down_sync(FULLM, sg, d);
        st += __shfl_down_sync(FULLM, st, d);
    }
    if (lane == 31) s_wosum[wid] = incl;
    if (lane == 0) { s_wg[wid] = sg; s_wt[wid] = st; }
    if (tid == 0) s_off0 = (int)(offm & 1u);
    __syncthreads();

    // ---- cross-warp prefix + scatter onset counts ----
    int wpre = 0;
#pragma unroll
    for (int w = 0; w < 8; w++) wpre += (w < wid) ? s_wosum[w] : 0;
    const int excl = wpre + incl - osum;   // exclusive prefix of this thread

    unsigned m = onm;
    if (tid == 0) m &= ~1u;                // reference masks onsets at idx==0
    while (m) {
        const int j = __ffs(m) - 1;
        m &= m - 1;
        const int seg = excl + __popc(offm & ((2u << j) - 1u));  // inclusive cumsum at l
        if (seg < NMAX) atomicAdd(&s_counts[seg], 1);
    }
    __syncthreads();

    // ---- per-note loss, block reduce ----
    int   n_notes = 0;
    float tg = 0.f, tt = 0.f;
#pragma unroll
    for (int w = 0; w < 8; w++) { n_notes += s_wosum[w]; tg += s_wg[w]; tt += s_wt[w]; }
    const float dd = (tg - tt) * (1.0f / LEN);

    float val = 0.f;
    if (tid < NMAX) {
        float c = -(float)s_counts[tid];
        if (tid == 0) c -= (float)s_off0;
        if (tid >= n_notes) c = 0.f;
        const float diff = fabsf(c * dd / (c + 1e-6f));
        val = fmaxf(diff - 0.5f, 0.f);
    }
#pragma unroll
    for (int d = 16; d > 0; d >>= 1) val += __shfl_down_sync(FULLM, val, d);
    if (lane == 0 && wid < 4) s_red[wid] = val;   // warps 0-3 hold tid<128
    __syncthreads();

    if (tid == 0) {
        g_partial[b] = (s_red[0] + s_red[1]) + (s_red[2] + s_red[3]);
        __threadfence();
        const int old = atomicAdd(&g_ticket, 1);
        s_islast = (old == BATCH - 1);   // no spin: only last arrival proceeds
    }
    __syncthreads();

    // ---- last block: reduce 64 partials, write output, rearm ticket ----
    if (s_islast) {
        float v = (tid < BATCH) ? g_partial[tid] : 0.f;
#pragma unroll
        for (int d = 16; d > 0; d >>= 1) v += __shfl_down_sync(FULLM, v, d);
        if (lane == 0 && wid < 2) s_red[wid] = v;
        __syncthreads();
        if (tid == 0) {
            out[0] = (s_red[0] + s_red[1]) * (1.0f / (NMAX * BATCH));
            g_ticket = 0;   // rearm for next graph replay
        }
    }
}

extern "C" void kernel_launch(void* const* d_in, const int* in_sizes, int n_in,
                              void* d_out, int out_size)
{
    const float* gen_f0   = (const float*)d_in[0];
    const float* contours = (const float*)d_in[1];
    const int*   onsets   = (const int*)d_in[2];
    const int*   offsets  = (const int*)d_in[3];
    // d_in[4] = n_notes_max (compile-time NMAX=128 for this shape)

    pitch_fused_kernel<<<BATCH, T1>>>(gen_f0, contours, onsets, offsets, (float*)d_out);
}

// round 4
// speedup vs baseline: 1.2385x; 1.0769x over previous
#include <cuda_runtime.h>
#include <cuda_bf16.h>

// PitchLoss: the reference's (N,B,L) broadcast collapses analytically because
// mask[n,b,l] = c[b,n] is constant over l:
//   diff[b,n] = | c[b,n] * (mean_g[b] - mean_t[b]) / (c[b,n] + 1e-6) |
//   loss      = mean_{b,n} relu(diff - 0.5)
// with c[b,n] = -(# onsets at idx>=1 in segment n) - (n==0 ? offsets[b,0] : 0),
// zeroed for n >= n_notes[b] = sum_l offsets[b,l]; segment index = inclusive
// cumsum of offsets. Single fused kernel, one block per row, ticket-based
// final reduce. R4 change: ALL 16 LDG.128s front-batched into register arrays
// so the full row transfer overlaps in one DRAM latency (R3 showed regs=38 ->
// ptxas had serialized the load chain, DRAM active only 6%).

#define BATCH 64
#define LEN   4096
#define NMAX  128
#define T1    256
#define CHUNK (LEN / T1)   // 16 elements / thread
#define NV    (CHUNK / 4)  // 4 x 128-bit loads per stream
#define FULLM 0xffffffffu

__device__ float g_partial[BATCH];
__device__ int   g_ticket = 0;

__global__ __launch_bounds__(T1)
void pitch_fused_kernel(const float* __restrict__ gen_f0,
                        const float* __restrict__ contours,
                        const int*   __restrict__ onsets,
                        const int*   __restrict__ offsets,
                        float*       __restrict__ out)
{
    const int b    = blockIdx.x;
    const int tid  = threadIdx.x;
    const int lane = tid & 31;
    const int wid  = tid >> 5;           // 8 warps

    const float4* gr  = (const float4*)(gen_f0   + (size_t)b * LEN)     + tid * NV;
    const float4* tr  = (const float4*)(contours + (size_t)b * 2 * LEN) + tid * NV;
    const int4*   on  = (const int4*)(onsets  + (size_t)b * LEN) + tid * NV;
    const int4*   off = (const int4*)(offsets + (size_t)b * LEN) + tid * NV;

    __shared__ int   s_counts[NMAX];
    __shared__ int   s_wosum[8];
    __shared__ float s_wg[8], s_wt[8];
    __shared__ float s_red[4];
    __shared__ int   s_off0;
    __shared__ int   s_islast;

    if (tid < NMAX) s_counts[tid] = 0;

    // ---- front-batched loads: all 16 LDG.128 issued before any consumption ----
    float4 g4[NV], t4[NV];
    int4   o4[NV], n4[NV];
#pragma unroll
    for (int j = 0; j < NV; j++) g4[j] = gr[j];
#pragma unroll
    for (int j = 0; j < NV; j++) t4[j] = tr[j];
#pragma unroll
    for (int j = 0; j < NV; j++) o4[j] = off[j];
#pragma unroll
    for (int j = 0; j < NV; j++) n4[j] = on[j];

    // ---- sums + 16-bit on/off masks ----
    float sg = 0.f, st = 0.f;
    unsigned offm = 0, onm = 0;
#pragma unroll
    for (int j = 0; j < NV; j++) {
        sg += (g4[j].x + g4[j].y) + (g4[j].z + g4[j].w);
        st += (t4[j].x + t4[j].y) + (t4[j].z + t4[j].w);
        const int s = 4 * j;
        offm |= ((unsigned)o4[j].x << s) | ((unsigned)o4[j].y << (s + 1))
              | ((unsigned)o4[j].z << (s + 2)) | ((unsigned)o4[j].w << (s + 3));
        onm  |= ((unsigned)n4[j].x << s) | ((unsigned)n4[j].y << (s + 1))
              | ((unsigned)n4[j].z << (s + 2)) | ((unsigned)n4[j].w << (s + 3));
    }
    const int osum = __popc(offm);

    // ---- warp-level: inclusive scan of osum, reduce sg/st ----
    int incl = osum;
#pragma unroll
    for (int d = 1; d < 32; d <<= 1) {
        int v = __shfl_up_sync(FULLM, incl, d);
        if (lane >= d) incl += v;
    }
#pragma unroll
    for (int d = 16; d > 0; d >>= 1) {
        sg += __shfl_down_sync(FULLM, sg, d);
        st += __shfl_down_sync(FULLM, st, d);
    }
    if (lane == 31) s_wosum[wid] = incl;
    if (lane == 0) { s_wg[wid] = sg; s_wt[wid] = st; }
    if (tid == 0) s_off0 = (int)(offm & 1u);
    __syncthreads();

    // ---- cross-warp prefix + scatter onset counts ----
    int wpre = 0;
#pragma unroll
    for (int w = 0; w < 8; w++) wpre += (w < wid) ? s_wosum[w] : 0;
    const int excl = wpre + incl - osum;   // exclusive prefix of this thread

    unsigned m = onm;
    if (tid == 0) m &= ~1u;                // reference masks onsets at idx==0
    while (m) {
        const int j = __ffs(m) - 1;
        m &= m - 1;
        const int seg = excl + __popc(offm & ((2u << j) - 1u));  // inclusive cumsum at l
        if (seg < NMAX) atomicAdd(&s_counts[seg], 1);
    }
    __syncthreads();

    // ---- per-note loss, block reduce ----
    int   n_notes = 0;
    float tg = 0.f, tt = 0.f;
#pragma unroll
    for (int w = 0; w < 8; w++) { n_notes += s_wosum[w]; tg += s_wg[w]; tt += s_wt[w]; }
    const float dd = (tg - tt) * (1.0f / LEN);

    float val = 0.f;
    if (tid < NMAX) {
        float c = -(float)s_counts[tid];
        if (tid == 0) c -= (float)s_off0;
        if (tid >= n_notes) c = 0.f;
        const float diff = fabsf(c * dd / (c + 1e-6f));
        val = fmaxf(diff - 0.5f, 0.f);
    }
#pragma unroll
    for (int d = 16; d > 0; d >>= 1) val += __shfl_down_sync(FULLM, val, d);
    if (lane == 0 && wid < 4) s_red[wid] = val;   // warps 0-3 hold tid<128
    __syncthreads();

    if (tid == 0) {
        g_partial[b] = (s_red[0] + s_red[1]) + (s_red[2] + s_red[3]);
        __threadfence();
        const int old = atomicAdd(&g_ticket, 1);
        s_islast = (old == BATCH - 1);   // no spin: only last arrival proceeds
    }
    __syncthreads();

    // ---- last block: reduce 64 partials, write output, rearm ticket ----
    if (s_islast) {
        float v = (tid < BATCH) ? g_partial[tid] : 0.f;
#pragma unroll
        for (int d = 16; d > 0; d >>= 1) v += __shfl_down_sync(FULLM, v, d);
        if (lane == 0 && wid < 2) s_red[wid] = v;
        __syncthreads();
        if (tid == 0) {
            out[0] = (s_red[0] + s_red[1]) * (1.0f / (NMAX * BATCH));
            g_ticket = 0;   // rearm for next graph replay
        }
    }
}

extern "C" void kernel_launch(void* const* d_in, const int* in_sizes, int n_in,
                              void* d_out, int out_size)
{
    const float* gen_f0   = (const float*)d_in[0];
    const float* contours = (const float*)d_in[1];
    const int*   onsets   = (const int*)d_in[2];
    const int*   offsets  = (const int*)d_in[3];
    // d_in[4] = n_notes_max (compile-time NMAX=128 for this shape)

    pitch_fused_kernel<<<BATCH, T1>>>(gen_f0, contours, onsets, offsets, (float*)d_out);
}